// round 5
// baseline (speedup 1.0000x reference)
#include <cuda_runtime.h>
#include <cuda_bf16.h>

// ANFIS fuzzy inference, batch=2M rows x 4 features.
// out = sum_j(w_j * clip(conseq_j)) / max(sum_j w_j, 1e-8),
// w_j = prod of 4 Gaussian memberships.
//
// Structure (best so far, R4) plus occupancy/latency tuning:
//  - exp2 prescale: mu_i = ex2(-(x*a'+b')^2), a' = (1/sigma)*sqrt(0.5*log2 e).
//  - pair-product CSE: P[9] = mu[0..2] x mu[3..5], Q[6] = mu[6..8] x mu[9..10].
//  - group factorization over the 6 shared Q factors.
//  - CSE'd unweighted group sums (u = P0+P1+P3, v = u+P2 reused by 4 groups).
//  - split accumulators (halve the 6-group serial FMA chain).
//  - 2 rows/thread, 256 threads, min 6 CTAs/SM for occupancy.

namespace {
// Rules grouped by q = (ante2-6)*2 + (ante3-9); p = ante0*3 + (ante1-3).
// Verified against RULE_ANTECEDENTS.
//   g0 (q=0): p {0,3,1,2,8,5,7}  cq {9,13,15,19,23,27,28}
//   g1 (q=1): p {8,7,5,4}        cq {22,24,25,29}
//   g2 (q=2): p {0,4,3,6,5}      cq {2,11,17,18,20}
//   g3 (q=3): p {0,1,3,2,8}      cq {4,10,12,14,26}
//   g4 (q=4): p {0,1,3,2,7}      cq {0,3,6,7,21}
//   g5 (q=5): p {0,1,3,4}        cq {1,5,8,16}
__device__ constexpr int GRP_OFF[7] = {0, 7, 11, 16, 21, 26, 30};
__device__ constexpr int GRP_P[30]  = {0,3,1,2,8,5,7,  8,7,5,4,  0,4,3,6,5,
                                       0,1,3,2,8,  0,1,3,2,7,  0,1,3,4};
__device__ constexpr int GRP_CQ[30] = {9,13,15,19,23,27,28,  22,24,25,29,
                                       2,11,17,18,20,  4,10,12,14,26,
                                       0,3,6,7,21,  1,5,8,16};
__device__ constexpr int DM[11] = {0,0,0,1,1,1,2,2,2,3,3};
}

// ex2(-t): sign flip (alu pipe) + MUFU.EX2.
__device__ __forceinline__ float ex2neg(float t) {
    float nt = __int_as_float(__float_as_int(t) ^ 0x80000000);
    float r; asm("ex2.approx.ftz.f32 %0, %1;" : "=f"(r) : "f"(nt)); return r;
}

constexpr int THREADS = 256;
constexpr int ROWS_PER_THREAD = 2;
constexpr int TILE = THREADS * ROWS_PER_THREAD;   // 512 rows/block

__device__ __forceinline__ float anfis_row(const float4 xv,
                                           const float* __restrict__ a,
                                           const float* __restrict__ b,
                                           const float* __restrict__ cq)
{
    const float xd[4] = {xv.x, xv.y, xv.z, xv.w};

    // 11 memberships: FFMA + FMUL + XOR + MUFU each.
    float mu[11];
    #pragma unroll
    for (int i = 0; i < 11; i++) {
        float d = fmaf(xd[DM[i]], a[i], b[i]);
        mu[i] = ex2neg(d * d);
    }

    // Pair products.
    float Pv[9], Qv[6];
    #pragma unroll
    for (int i = 0; i < 3; i++)
        #pragma unroll
        for (int j = 0; j < 3; j++)
            Pv[i * 3 + j] = mu[i] * mu[3 + j];
    #pragma unroll
    for (int i = 0; i < 3; i++)
        #pragma unroll
        for (int j = 0; j < 2; j++)
            Qv[i * 2 + j] = mu[6 + i] * mu[9 + j];

    // Weighted group inner sums (cq coefficients differ; no CSE possible).
    float s1[6];
    #pragma unroll
    for (int g = 0; g < 6; g++) {
        const int m0 = GRP_OFF[g], m1 = GRP_OFF[g + 1];
        float s = Pv[GRP_P[m0]] * cq[GRP_CQ[m0]];
        #pragma unroll
        for (int m = m0 + 1; m < m1; m++)
            s = fmaf(Pv[GRP_P[m]], cq[GRP_CQ[m]], s);
        s1[g] = s;
    }

    // Unweighted group sums with CSE.
    float u = (Pv[0] + Pv[1]) + Pv[3];   // {0,1,3}
    float v = u + Pv[2];                 // {0,1,3,2}
    float s0_0 = v + ((Pv[8] + Pv[5]) + Pv[7]);
    float s0_1 = (Pv[8] + Pv[7]) + (Pv[5] + Pv[4]);
    float s0_2 = ((Pv[0] + Pv[4]) + (Pv[3] + Pv[6])) + Pv[5];
    float s0_3 = v + Pv[8];
    float s0_4 = v + Pv[7];
    float s0_5 = u + Pv[4];

    // Split accumulators: two independent 3-FMA chains each.
    float accA = Qv[0] * s1[0];
    float accB = Qv[1] * s1[1];
    accA = fmaf(Qv[2], s1[2], accA);
    accB = fmaf(Qv[3], s1[3], accB);
    accA = fmaf(Qv[4], s1[4], accA);
    accB = fmaf(Qv[5], s1[5], accB);

    float wsA = Qv[0] * s0_0;
    float wsB = Qv[1] * s0_1;
    wsA = fmaf(Qv[2], s0_2, wsA);
    wsB = fmaf(Qv[3], s0_3, wsB);
    wsA = fmaf(Qv[4], s0_4, wsA);
    wsB = fmaf(Qv[5], s0_5, wsB);

    return __fdividef(accA + accB, fmaxf(wsA + wsB, 1e-8f));
}

__global__ void __launch_bounds__(THREADS, 6)
anfis_kernel(const float4* __restrict__ x,
             const float*  __restrict__ c,
             const float*  __restrict__ log_s,
             const float*  __restrict__ conseq,
             float* __restrict__ out,
             int n)
{
    // Per-block constants staged via smem; ptxas keeps hot ones in registers.
    __shared__ float s_a[11], s_b[11], s_cq[30];

    const int t = threadIdx.x;
    if (t < 11) {
        const float KS = 0.8493218002880191f;  // sqrt(0.5 * log2(e))
        float ci  = __ldg(c + t);
        float sg  = fmaxf(__expf(__ldg(log_s + t)), 0.001f);
        float ap  = KS / sg;
        s_a[t] = ap;
        s_b[t] = -ci * ap;
    }
    if (t < 30) {
        s_cq[t] = fminf(fmaxf(__ldg(conseq + t), 0.0f), 100.0f);
    }
    __syncthreads();

    float a[11], b[11];
    #pragma unroll
    for (int i = 0; i < 11; i++) { a[i] = s_a[i]; b[i] = s_b[i]; }

    const int base = blockIdx.x * TILE + t;

    if (blockIdx.x * TILE + TILE <= n) {
        // Full tile: unconditional coalesced LDG.128 (MLP=2 per thread).
        float4 xv[ROWS_PER_THREAD];
        #pragma unroll
        for (int k = 0; k < ROWS_PER_THREAD; k++)
            xv[k] = __ldg(x + base + k * THREADS);

        float res[ROWS_PER_THREAD];
        #pragma unroll
        for (int k = 0; k < ROWS_PER_THREAD; k++)
            res[k] = anfis_row(xv[k], a, b, s_cq);

        #pragma unroll
        for (int k = 0; k < ROWS_PER_THREAD; k++)
            out[base + k * THREADS] = res[k];
    } else {
        // Tail: predicated.
        #pragma unroll
        for (int k = 0; k < ROWS_PER_THREAD; k++) {
            int r = base + k * THREADS;
            if (r < n) {
                float4 xv = __ldg(x + r);
                out[r] = anfis_row(xv, a, b, s_cq);
            }
        }
    }
}

extern "C" void kernel_launch(void* const* d_in, const int* in_sizes, int n_in,
                              void* d_out, int out_size)
{
    const float* x      = (const float*)d_in[0];
    const float* c      = (const float*)d_in[1];
    const float* log_s  = (const float*)d_in[2];
    const float* conseq = (const float*)d_in[3];
    float* out          = (float*)d_out;

    int n = in_sizes[0] / 4;   // rows
    int blocks = (n + TILE - 1) / TILE;

    anfis_kernel<<<blocks, THREADS>>>((const float4*)x, c, log_s, conseq, out, n);
}

// round 7
// speedup vs baseline: 1.2736x; 1.2736x over previous
#include <cuda_runtime.h>
#include <cuda_bf16.h>

// ANFIS fuzzy inference, batch=2M rows x 4 features.
// out = sum_j(w_j * clip(conseq_j)) / max(sum_j w_j, 1e-8),
// w_j = prod of 4 Gaussian memberships.
//
// R4 shell (constants register-resident, 4 rows/thread, natural regalloc)
// with refined row math:
//  - exp2 prescale: mu_i = ex2((-d)*d), d = x*a'+b', a' = (1/sigma)*sqrt(0.5*log2 e)
//    (negation folded into the FMUL source modifier — no XOR/LOP3).
//  - pair-product CSE: P[9] = mu[0..2] x mu[3..5], Q[6] = mu[6..8] x mu[9..10].
//  - group factorization over the 6 shared Q factors.
//  - CSE'd unweighted group sums (u = P0+P1+P3, v = u+P2 feed 4 groups).
//  - split accumulators (two independent FMA chains for acc and wsum).
//  - 128-thread blocks: finer CTA packing at ~46 regs (11 CTAs/SM).

namespace {
// Rules grouped by q = (ante2-6)*2 + (ante3-9); p = ante0*3 + (ante1-3).
// Verified against RULE_ANTECEDENTS.
__device__ constexpr int GRP_OFF[7] = {0, 7, 11, 16, 21, 26, 30};
__device__ constexpr int GRP_P[30]  = {0,3,1,2,8,5,7,  8,7,5,4,  0,4,3,6,5,
                                       0,1,3,2,8,  0,1,3,2,7,  0,1,3,4};
__device__ constexpr int GRP_CQ[30] = {9,13,15,19,23,27,28,  22,24,25,29,
                                       2,11,17,18,20,  4,10,12,14,26,
                                       0,3,6,7,21,  1,5,8,16};
__device__ constexpr int DM[11] = {0,0,0,1,1,1,2,2,2,3,3};
}

__device__ __forceinline__ float ex2(float t) {
    float r; asm("ex2.approx.ftz.f32 %0, %1;" : "=f"(r) : "f"(t)); return r;
}

constexpr int THREADS = 128;
constexpr int ROWS_PER_THREAD = 4;
constexpr int TILE = THREADS * ROWS_PER_THREAD;   // 512 rows/block

__device__ __forceinline__ float anfis_row(const float4 xv,
                                           const float* __restrict__ a,
                                           const float* __restrict__ b,
                                           const float* __restrict__ cq)
{
    const float xd[4] = {xv.x, xv.y, xv.z, xv.w};

    // 11 memberships: FFMA + FMUL(neg-src) + MUFU each.
    float mu[11];
    #pragma unroll
    for (int i = 0; i < 11; i++) {
        float d = fmaf(xd[DM[i]], a[i], b[i]);
        mu[i] = ex2(-d * d);       // negation folds into FMUL operand
    }

    // Pair products.
    float Pv[9], Qv[6];
    #pragma unroll
    for (int i = 0; i < 3; i++)
        #pragma unroll
        for (int j = 0; j < 3; j++)
            Pv[i * 3 + j] = mu[i] * mu[3 + j];
    #pragma unroll
    for (int i = 0; i < 3; i++)
        #pragma unroll
        for (int j = 0; j < 2; j++)
            Qv[i * 2 + j] = mu[6 + i] * mu[9 + j];

    // Weighted group inner sums (distinct cq per term; 6 MUL + 24 FMA).
    float s1[6];
    #pragma unroll
    for (int g = 0; g < 6; g++) {
        const int m0 = GRP_OFF[g], m1 = GRP_OFF[g + 1];
        float s = Pv[GRP_P[m0]] * cq[GRP_CQ[m0]];
        #pragma unroll
        for (int m = m0 + 1; m < m1; m++)
            s = fmaf(Pv[GRP_P[m]], cq[GRP_CQ[m]], s);
        s1[g] = s;
    }

    // Unweighted group sums with CSE (16 ADDs).
    float u = (Pv[0] + Pv[1]) + Pv[3];   // {0,1,3}
    float v = u + Pv[2];                 // {0,1,2,3}
    float s0_0 = v + ((Pv[8] + Pv[5]) + Pv[7]);
    float s0_1 = (Pv[8] + Pv[7]) + (Pv[5] + Pv[4]);
    float s0_2 = ((Pv[0] + Pv[4]) + (Pv[3] + Pv[6])) + Pv[5];
    float s0_3 = v + Pv[8];
    float s0_4 = v + Pv[7];
    float s0_5 = u + Pv[4];

    // Split accumulators: two independent 3-op chains each.
    float accA = Qv[0] * s1[0];
    float accB = Qv[1] * s1[1];
    accA = fmaf(Qv[2], s1[2], accA);
    accB = fmaf(Qv[3], s1[3], accB);
    accA = fmaf(Qv[4], s1[4], accA);
    accB = fmaf(Qv[5], s1[5], accB);

    float wsA = Qv[0] * s0_0;
    float wsB = Qv[1] * s0_1;
    wsA = fmaf(Qv[2], s0_2, wsA);
    wsB = fmaf(Qv[3], s0_3, wsB);
    wsA = fmaf(Qv[4], s0_4, wsA);
    wsB = fmaf(Qv[5], s0_5, wsB);

    return __fdividef(accA + accB, fmaxf(wsA + wsB, 1e-8f));
}

__global__ void __launch_bounds__(THREADS)
anfis_kernel(const float4* __restrict__ x,
             const float*  __restrict__ c,
             const float*  __restrict__ log_s,
             const float*  __restrict__ conseq,
             float* __restrict__ out,
             int n)
{
    // Per-block constants staged via smem, then held in registers
    // (natural register allocation — no occupancy clamp; see R5 post-mortem).
    __shared__ float s_a[11], s_b[11], s_cq[30];

    const int t = threadIdx.x;
    if (t < 11) {
        const float KS = 0.8493218002880191f;  // sqrt(0.5 * log2(e))
        float ci  = __ldg(c + t);
        float sg  = fmaxf(__expf(__ldg(log_s + t)), 0.001f);
        float ap  = KS / sg;
        s_a[t] = ap;
        s_b[t] = -ci * ap;
    }
    if (t < 30) {
        s_cq[t] = fminf(fmaxf(__ldg(conseq + t), 0.0f), 100.0f);
    }
    __syncthreads();

    float a[11], b[11];
    #pragma unroll
    for (int i = 0; i < 11; i++) { a[i] = s_a[i]; b[i] = s_b[i]; }

    const int base = blockIdx.x * TILE + t;
    const bool full = (blockIdx.x * TILE + TILE <= n);

    if (full) {
        // Full tile: 4 unconditional coalesced LDG.128 (MLP=4).
        float4 xv[ROWS_PER_THREAD];
        #pragma unroll
        for (int k = 0; k < ROWS_PER_THREAD; k++)
            xv[k] = __ldg(x + base + k * THREADS);

        float res[ROWS_PER_THREAD];
        #pragma unroll
        for (int k = 0; k < ROWS_PER_THREAD; k++)
            res[k] = anfis_row(xv[k], a, b, s_cq);

        #pragma unroll
        for (int k = 0; k < ROWS_PER_THREAD; k++)
            out[base + k * THREADS] = res[k];
    } else {
        // Tail: predicated.
        #pragma unroll
        for (int k = 0; k < ROWS_PER_THREAD; k++) {
            int r = base + k * THREADS;
            if (r < n) {
                float4 xv = __ldg(x + r);
                out[r] = anfis_row(xv, a, b, s_cq);
            }
        }
    }
}

extern "C" void kernel_launch(void* const* d_in, const int* in_sizes, int n_in,
                              void* d_out, int out_size)
{
    const float* x      = (const float*)d_in[0];
    const float* c      = (const float*)d_in[1];
    const float* log_s  = (const float*)d_in[2];
    const float* conseq = (const float*)d_in[3];
    float* out          = (float*)d_out;

    int n = in_sizes[0] / 4;   // rows
    int blocks = (n + TILE - 1) / TILE;

    anfis_kernel<<<blocks, THREADS>>>((const float4*)x, c, log_s, conseq, out, n);
}